// round 13
// baseline (speedup 1.0000x reference)
#include <cuda_runtime.h>
#include <cuda_bf16.h>

// Problem constants
#define Bx 4
#define Cx 3
#define Hx 224
#define Wx 224
#define Kx 196
#define Ex 768
#define HW (Hx * Wx)               // 50176
#define KC (Kx * Cx)               // 588
#define BK (Bx * Kx)               // 784

#define BPB 74                     // blocks per batch; 4*74 = 296 = 2 per SM
#define NBLK (Bx * BPB)            // 296
#define TA 256
#define F4_PER_BLOCK 170           // 73*170 + 134 = 12544 = HW/4
#define F4_LAST 134

#define COLS_PER_THREAD (Ex / TA)  // 3
#define MAXROWS 3                  // phase-2 rows per block

#define NREP 4                     // replicated global pools (L2 contention spread)
#define ROW_F4 8                   // 128 B per (b,k) row

// Replicated pooled sums: g_pool4[rep][bk][ROW_F4]; element 0 = {c0,c1,c2,pad}.
// Zero at module load; phase 2 re-zeroes consumed rows each call.
__device__ float4 g_pool4[NREP * BK * ROW_F4];

// Per-batch sub-barriers: monotone epoch counters, 128 B apart. u64 -> no overflow.
__device__ unsigned long long g_bar[Bx * 16];

__device__ __forceinline__ void red_add_v4(float4* p, float x, float y, float z) {
    asm volatile("red.global.add.v4.f32 [%0], {%1, %2, %3, %4};"
                 :: "l"(p), "f"(x), "f"(y), "f"(z), "f"(0.0f) : "memory");
}

__device__ __forceinline__ float4 ldcg4(const float4* p) {
    float4 v;
    asm volatile("ld.global.cg.v4.f32 {%0,%1,%2,%3}, [%4];"
                 : "=f"(v.x), "=f"(v.y), "=f"(v.z), "=f"(v.w) : "l"(p));
    return v;
}

__global__ void __launch_bounds__(TA)
fused_kernel(const float* __restrict__ img,
             const int* __restrict__ seg,
             const float* __restrict__ Wmat,
             const float* __restrict__ bias,
             float* __restrict__ out) {
    __shared__ float s_pool[KC];

    const int tid = threadIdx.x;
    const int b   = blockIdx.x / BPB;
    const int j   = blockIdx.x % BPB;
    const int rep = blockIdx.x & (NREP - 1);

    // ---------------- Phase 1: hybrid segment-sum ----------------
    for (int i = tid; i < KC; i += TA) s_pool[i] = 0.0f;
    __syncthreads();

    const int nf4 = (j < BPB - 1) ? F4_PER_BLOCK : F4_LAST;
    const float* img_b = img + (size_t)b * Cx * HW;
    const int*   seg_b = seg + (size_t)b * HW;
    float4* pool_rb = g_pool4 + ((size_t)rep * BK + (size_t)b * Kx) * ROW_F4;

    if (tid < nf4) {
        const int p0 = (j * F4_PER_BLOCK + tid) * 4;

        int4   s  = *(const int4*)  (seg_b + p0);
        float4 v0 = *(const float4*)(img_b + p0);
        float4 v1 = *(const float4*)(img_b + p0 + HW);
        float4 v2 = *(const float4*)(img_b + p0 + 2 * HW);

        // Pixels x,y -> shared-memory atomics (per-SM LSU unit)
        atomicAdd(&s_pool[s.x * Cx + 0], v0.x);
        atomicAdd(&s_pool[s.x * Cx + 1], v1.x);
        atomicAdd(&s_pool[s.x * Cx + 2], v2.x);
        atomicAdd(&s_pool[s.y * Cx + 0], v0.y);
        atomicAdd(&s_pool[s.y * Cx + 1], v1.y);
        atomicAdd(&s_pool[s.y * Cx + 2], v2.y);

        // Pixels z,w -> fire-and-forget L2 vector reductions (L2 atomic ALU)
        red_add_v4(pool_rb + s.z * ROW_F4, v0.z, v1.z, v2.z);
        red_add_v4(pool_rb + s.w * ROW_F4, v0.w, v1.w, v2.w);
    }

    __syncthreads();

    // Flush block partials: one fire-and-forget v4 RED per key, to this
    // block's replica (spreads L2 per-address contention 4x).
    if (tid < Kx) {
        float c0 = s_pool[tid * Cx + 0];
        float c1 = s_pool[tid * Cx + 1];
        float c2 = s_pool[tid * Cx + 2];
        red_add_v4(pool_rb + tid * ROW_F4, c0, c1, c2);
    }

    // Prefetch phase-2 operands (independent of the barrier)
    float w0c[COLS_PER_THREAD], w1c[COLS_PER_THREAD], w2c[COLS_PER_THREAD];
    float bbc[COLS_PER_THREAD];
#pragma unroll
    for (int jj = 0; jj < COLS_PER_THREAD; jj++) {
        int e = tid + jj * TA;
        w0c[jj] = Wmat[0 * Ex + e];
        w1c[jj] = Wmat[1 * Ex + e];
        w2c[jj] = Wmat[2 * Ex + e];
        bbc[jj] = bias[e];
    }

    // ---------------- Per-batch sub-barrier (74 arrivals; proven form) -----
    __threadfence();                       // REDs globally visible first
    if (tid == 0) {
        unsigned long long* bar = &g_bar[b * 16];
        unsigned long long old = atomicAdd(bar, 1ULL);
        unsigned long long target = (old / BPB + 1ULL) * BPB;
        while (*(volatile unsigned long long*)bar < target) { }
    }
    __syncthreads();
    // Phase-2 pooled reads use ld.global.cg (L2 is the coherence point).

    // ---------------- Phase 2: rows j, j+74, j+148 of this batch ------------
    const float inv = 1.0f / (float)HW;

    float4 q[MAXROWS][NREP];
#pragma unroll
    for (int i = 0; i < MAXROWS; i++) {
        int r = j + BPB * i;
        if (r < Kx) {
#pragma unroll
            for (int rp = 0; rp < NREP; rp++) {
                q[i][rp] = ldcg4(&g_pool4[((size_t)rp * BK + b * Kx + r) * ROW_F4]);
            }
        }
    }

#pragma unroll
    for (int i = 0; i < MAXROWS; i++) {
        int r = j + BPB * i;
        if (r < Kx) {
            const int bk = b * Kx + r;
            float p0 = 0.f, p1 = 0.f, p2 = 0.f;
#pragma unroll
            for (int rp = 0; rp < NREP; rp++) {
                p0 += q[i][rp].x; p1 += q[i][rp].y; p2 += q[i][rp].z;
            }
            p0 *= inv; p1 *= inv; p2 *= inv;
#pragma unroll
            for (int jj = 0; jj < COLS_PER_THREAD; jj++) {
                int e = tid + jj * TA;
                float acc = bbc[jj];
                acc = fmaf(p0, w0c[jj], acc);
                acc = fmaf(p1, w1c[jj], acc);
                acc = fmaf(p2, w2c[jj], acc);
                out[(size_t)bk * Ex + e] = acc;
            }
        }
    }

    // Restore the zero-invariant for all replicas of the rows this block read.
    __syncthreads();
    if (tid < MAXROWS * NREP) {
        const int i  = tid >> 2;           // 0..2
        const int rp = tid & 3;
        const int r  = j + BPB * i;
        if (r < Kx) {
            g_pool4[((size_t)rp * BK + b * Kx + r) * ROW_F4] =
                make_float4(0.f, 0.f, 0.f, 0.f);
        }
    }
}

extern "C" void kernel_launch(void* const* d_in, const int* in_sizes, int n_in,
                              void* d_out, int out_size) {
    const float* img  = (const float*)d_in[0];
    const int*   seg  = (const int*)d_in[1];
    const float* Wmat = (const float*)d_in[2];
    const float* bias = (const float*)d_in[3];
    float* out = (float*)d_out;

    fused_kernel<<<NBLK, TA>>>(img, seg, Wmat, bias, out);
}